// round 1
// baseline (speedup 1.0000x reference)
#include <cuda_runtime.h>
#include <cuda_bf16.h>
#include <cstdint>

// Problem constants
#define B_DIM   4096
#define IN_DIM  2048
#define OUT_DIM 2048
#define K_DIM   4096           // concat: [xn | S]
#define GRID_SZ 8

// LUT for S(xn) = sum_g exp(-beta*(xn-g)^2)
#define LUT_N    8192
#define LUT_LO   (-8.0f)
#define LUT_HI   (8.0f)
#define LUT_STEP ((LUT_HI - LUT_LO) / (float)LUT_N)
#define LUT_INV  ((float)LUT_N / (LUT_HI - LUT_LO))

// Scratch (allocation-free rule: __device__ globals)
__device__ float g_A[(size_t)B_DIM * K_DIM];     // 64 MB: [b][k] k<2048: xn, k>=2048: S
__device__ float g_B[(size_t)OUT_DIM * K_DIM];   // 32 MB: [o][k] k<2048: scale_base, k>=2048: Wd
__device__ float g_lut[LUT_N + 2];

// ---------------------------------------------------------------------------
// Kernel 1: build S lookup table
// ---------------------------------------------------------------------------
__global__ void lut_build_kernel(const float* __restrict__ grid,
                                 const float* __restrict__ rbf_beta) {
    int j = blockIdx.x * 256 + threadIdx.x;
    if (j > LUT_N) return;
    float beta = fminf(fmaxf(rbf_beta[0], 0.5f), 6.0f);
    float xx = LUT_LO + (float)j * LUT_STEP;
    float s = 0.f;
#pragma unroll
    for (int g = 0; g < GRID_SZ; g++) {
        float d = xx - grid[g];
        s += expf(-beta * d * d);
    }
    g_lut[j] = s;
}

// ---------------------------------------------------------------------------
// Kernel 2: LayerNorm + S via LUT  ->  g_A = [xn | S]
// one warp per row; 8 warps per block; LUT staged in shared
// ---------------------------------------------------------------------------
__global__ __launch_bounds__(256) void ln_s_kernel(const float* __restrict__ x,
                                                   const float* __restrict__ lw,
                                                   const float* __restrict__ lb) {
    __shared__ float lut_s[LUT_N + 2];
    for (int j = threadIdx.x; j <= LUT_N; j += 256) lut_s[j] = g_lut[j];
    __syncthreads();

    const int warp = threadIdx.x >> 5;
    const int lane = threadIdx.x & 31;
    const int row = blockIdx.x * 8 + warp;
    const float* xr = x + (size_t)row * IN_DIM;

    float s = 0.f, ss = 0.f;
    for (int j = lane; j < IN_DIM; j += 32) {
        float v = xr[j];
        s += v;
        ss = fmaf(v, v, ss);
    }
#pragma unroll
    for (int o = 16; o > 0; o >>= 1) {
        s  += __shfl_xor_sync(0xFFFFFFFFu, s, o);
        ss += __shfl_xor_sync(0xFFFFFFFFu, ss, o);
    }
    const float mean = s * (1.f / (float)IN_DIM);
    const float var  = ss * (1.f / (float)IN_DIM) - mean * mean;
    const float rstd = rsqrtf(var + 1e-5f);

    float* Ar = g_A + (size_t)row * K_DIM;
    for (int j = lane; j < IN_DIM; j += 32) {
        float xn = fmaf((xr[j] - mean) * rstd, lw[j], lb[j]);
        Ar[j] = xn;
        float t = (xn - LUT_LO) * LUT_INV;
        t = fminf(fmaxf(t, 0.f), (float)LUT_N - 0.001f);
        int i0 = (int)t;
        float fr = t - (float)i0;
        float s0 = lut_s[i0];
        Ar[IN_DIM + j] = fmaf(fr, lut_s[i0 + 1] - s0, s0);
    }
}

// ---------------------------------------------------------------------------
// Kernel 3: build B = [scale_base | Wd],  Wd[o][i] = sum_g spline[o][i][g]
// ---------------------------------------------------------------------------
__global__ __launch_bounds__(256) void build_b_kernel(const float* __restrict__ sw,
                                                      const float* __restrict__ sb) {
    size_t idx = (size_t)blockIdx.x * 256 + threadIdx.x;   // < OUT_DIM*IN_DIM
    const float4* p = (const float4*)(sw + idx * GRID_SZ);
    float4 w0 = p[0], w1 = p[1];
    float wd = ((w0.x + w0.y) + (w0.z + w0.w)) + ((w1.x + w1.y) + (w1.z + w1.w));
    size_t o = idx >> 11;        // /2048
    size_t i = idx & 2047;
    g_B[o * K_DIM + IN_DIM + i] = wd;
    g_B[o * K_DIM + i] = sb[idx];
}

// ---------------------------------------------------------------------------
// Kernel 4: TF32 GEMM  out[4096][2048] = g_A (4096xK) * g_B^T (2048xK) + bias
// 128x128 tile, BK=16, double-buffered cp.async, 8 warps (4Mx2N), warp 32x64
// ---------------------------------------------------------------------------
#define BM 128
#define BN 128
#define BK 16
#define SPAD 20   // BK + 4: conflict-free for the m16n8k8 fragment pattern

__device__ __forceinline__ uint32_t f2tf32(float v) {
    uint32_t r;
    asm("cvt.rna.tf32.f32 %0, %1;" : "=r"(r) : "f"(v));
    return r;
}

__device__ __forceinline__ void cp16(void* smem, const void* gmem) {
    uint32_t s = (uint32_t)__cvta_generic_to_shared(smem);
    asm volatile("cp.async.cg.shared.global [%0], [%1], 16;\n" :: "r"(s), "l"(gmem));
}

__device__ __forceinline__ void mma_tf32(float* c, const uint32_t* a, const uint32_t* b) {
    asm volatile(
        "mma.sync.aligned.m16n8k8.row.col.f32.tf32.tf32.f32 "
        "{%0,%1,%2,%3}, {%4,%5,%6,%7}, {%8,%9}, {%0,%1,%2,%3};\n"
        : "+f"(c[0]), "+f"(c[1]), "+f"(c[2]), "+f"(c[3])
        : "r"(a[0]), "r"(a[1]), "r"(a[2]), "r"(a[3]), "r"(b[0]), "r"(b[1]));
}

__global__ __launch_bounds__(256) void gemm_kernel(const float* __restrict__ bias,
                                                   float* __restrict__ C) {
    __shared__ float As[2][BM][SPAD];
    __shared__ float Bs[2][BN][SPAD];

    const int tid  = threadIdx.x;
    const int warp = tid >> 5;
    const int lane = tid & 31;
    const int wm = warp >> 1;    // 0..3 -> M
    const int wn = warp & 1;     // 0..1 -> N
    const int M0 = blockIdx.y * BM;
    const int N0 = blockIdx.x * BN;

    // global load mapping: 256 threads cover 64 rows x 16 cols per pass; 2 passes
    const int lrow  = tid >> 2;        // 0..63
    const int lcol  = (tid & 3) * 4;   // 0,4,8,12
    const float* Ag = g_A + (size_t)M0 * K_DIM + lcol;
    const float* Bg = g_B + (size_t)N0 * K_DIM + lcol;

    float c[2][8][4];
#pragma unroll
    for (int mi = 0; mi < 2; mi++)
#pragma unroll
        for (int ni = 0; ni < 8; ni++)
#pragma unroll
            for (int q = 0; q < 4; q++) c[mi][ni][q] = 0.f;

    auto issue = [&](int buf, int kt) {
        const int koff = kt * BK;
#pragma unroll
        for (int r = 0; r < 2; r++) {
            int row = lrow + r * 64;
            cp16(&As[buf][row][lcol], Ag + (size_t)row * K_DIM + koff);
            cp16(&Bs[buf][row][lcol], Bg + (size_t)row * K_DIM + koff);
        }
        asm volatile("cp.async.commit_group;\n" ::);
    };

    const int NT = K_DIM / BK;   // 256
    issue(0, 0);

    for (int kt = 0; kt < NT; kt++) {
        const int buf = kt & 1;
        if (kt + 1 < NT) {
            issue(buf ^ 1, kt + 1);
            asm volatile("cp.async.wait_group 1;\n" ::);
        } else {
            asm volatile("cp.async.wait_group 0;\n" ::);
        }
        __syncthreads();

#pragma unroll
        for (int ks = 0; ks < 2; ks++) {
            const int k0 = ks * 8;
            uint32_t af[2][4];
            uint32_t bf[8][2];
            const int ar = wm * 32;
#pragma unroll
            for (int mi = 0; mi < 2; mi++) {
                int r = ar + mi * 16 + (lane >> 2);
                int kc = k0 + (lane & 3);
                af[mi][0] = f2tf32(As[buf][r][kc]);
                af[mi][1] = f2tf32(As[buf][r + 8][kc]);
                af[mi][2] = f2tf32(As[buf][r][kc + 4]);
                af[mi][3] = f2tf32(As[buf][r + 8][kc + 4]);
            }
            const int nb = wn * 64;
#pragma unroll
            for (int ni = 0; ni < 8; ni++) {
                int nn = nb + ni * 8 + (lane >> 2);
                int kc = k0 + (lane & 3);
                bf[ni][0] = f2tf32(Bs[buf][nn][kc]);
                bf[ni][1] = f2tf32(Bs[buf][nn][kc + 4]);
            }
#pragma unroll
            for (int mi = 0; mi < 2; mi++)
#pragma unroll
                for (int ni = 0; ni < 8; ni++)
                    mma_tf32(c[mi][ni], af[mi], bf[ni]);
        }
        __syncthreads();
    }

    // epilogue: + bias, store fp32
#pragma unroll
    for (int mi = 0; mi < 2; mi++) {
#pragma unroll
        for (int ni = 0; ni < 8; ni++) {
            int r  = M0 + wm * 32 + mi * 16 + (lane >> 2);
            int cc = N0 + wn * 64 + ni * 8 + (lane & 3) * 2;
            float b0 = bias[cc], b1 = bias[cc + 1];
            C[(size_t)r * OUT_DIM + cc]           = c[mi][ni][0] + b0;
            C[(size_t)r * OUT_DIM + cc + 1]       = c[mi][ni][1] + b1;
            C[(size_t)(r + 8) * OUT_DIM + cc]     = c[mi][ni][2] + b0;
            C[(size_t)(r + 8) * OUT_DIM + cc + 1] = c[mi][ni][3] + b1;
        }
    }
}

// ---------------------------------------------------------------------------
extern "C" void kernel_launch(void* const* d_in, const int* in_sizes, int n_in,
                              void* d_out, int out_size) {
    const float* x    = (const float*)d_in[0];
    const float* lw   = (const float*)d_in[1];
    const float* lb   = (const float*)d_in[2];
    const float* sw   = (const float*)d_in[3];
    const float* sb   = (const float*)d_in[4];
    const float* bias = (const float*)d_in[5];
    const float* beta = (const float*)d_in[6];
    const float* grid = (const float*)d_in[7];
    float* out = (float*)d_out;

    lut_build_kernel<<<(LUT_N + 256) / 256, 256>>>(grid, beta);
    ln_s_kernel<<<B_DIM / 8, 256>>>(x, lw, lb);
    build_b_kernel<<<(OUT_DIM * IN_DIM) / 256, 256>>>(sw, sb);
    gemm_kernel<<<dim3(OUT_DIM / BN, B_DIM / BM), 256>>>(bias, out);
}

// round 3
// speedup vs baseline: 1.4748x; 1.4748x over previous
#include <cuda_runtime.h>
#include <cuda_bf16.h>
#include <cstdint>

// Problem constants
#define B_DIM   4096
#define IN_DIM  2048
#define OUT_DIM 2048
#define K_DIM   4096           // concat: [xn | S]
#define GRID_SZ 8
#define NKB     (K_DIM / 8)    // 512 k-blocks of 8

// LUT for S(xn) = sum_g exp(-beta*(xn-g)^2)
#define LUT_N    8192
#define LUT_LO   (-8.0f)
#define LUT_HI   (8.0f)
#define LUT_STEP ((LUT_HI - LUT_LO) / (float)LUT_N)
#define LUT_INV  ((float)LUT_N / (LUT_HI - LUT_LO))

// GEMM tiling
#define BM 128
#define BN 128
#define BK 32
#define NT (K_DIM / BK)        // 128 k-slabs
#define NSTAGE 3
#define STG_BYTES 32768        // A 16K + B 16K
#define SB_OFF 16384

// ---------------------------------------------------------------------------
// Scratch: fragment-major tf32 operands
//   A: [rb(256)][kb(512)][lane(32)][quad(4)]  (m16n8k8 A-fragment order)
//   B: [cb(256)][kb(512)][lane(32)][pair(2)]  (m16n8k8 B-fragment order)
// ---------------------------------------------------------------------------
__device__ float g_A[(size_t)B_DIM * K_DIM];     // 64 MB
__device__ float g_B[(size_t)OUT_DIM * K_DIM];   // 32 MB
__device__ float g_lut[LUT_N + 2];

__device__ __forceinline__ float rtf32(float v) {
    uint32_t r;
    asm("cvt.rna.tf32.f32 %0, %1;" : "=r"(r) : "f"(v));
    return __uint_as_float(r);
}

__device__ __forceinline__ void cp16(uint32_t saddr, const void* g) {
    asm volatile("cp.async.cg.shared.global [%0], [%1], 16;" :: "r"(saddr), "l"(g));
}

__device__ __forceinline__ uint32_t smem_u32(const void* p) {
    uint32_t a;
    asm("{ .reg .u64 t; cvta.to.shared.u64 t, %1; cvt.u32.u64 %0, t; }" : "=r"(a) : "l"(p));
    return a;
}

__device__ __forceinline__ void mma_tf32(float* c, const float4 a, const float2 b) {
    asm volatile(
        "mma.sync.aligned.m16n8k8.row.col.f32.tf32.tf32.f32 "
        "{%0,%1,%2,%3}, {%4,%5,%6,%7}, {%8,%9}, {%0,%1,%2,%3};\n"
        : "+f"(c[0]), "+f"(c[1]), "+f"(c[2]), "+f"(c[3])
        : "r"(__float_as_uint(a.x)), "r"(__float_as_uint(a.y)),
          "r"(__float_as_uint(a.z)), "r"(__float_as_uint(a.w)),
          "r"(__float_as_uint(b.x)), "r"(__float_as_uint(b.y)));
}

// ---------------------------------------------------------------------------
// Kernel 1: build S lookup table
// ---------------------------------------------------------------------------
__global__ void lut_build_kernel(const float* __restrict__ grid,
                                 const float* __restrict__ rbf_beta) {
    int j = blockIdx.x * 256 + threadIdx.x;
    if (j > LUT_N) return;
    float beta = fminf(fmaxf(rbf_beta[0], 0.5f), 6.0f);
    float xx = LUT_LO + (float)j * LUT_STEP;
    float s = 0.f;
#pragma unroll
    for (int g = 0; g < GRID_SZ; g++) {
        float d = xx - grid[g];
        s += expf(-beta * d * d);
    }
    g_lut[j] = s;
}

// ---------------------------------------------------------------------------
// Kernel 2: LayerNorm + S -> g_A in fragment-major layout, tf32-rounded.
// Block = 512 threads = 16 warps = 16 rows (one rb). 4 column panels of 512.
// smem: lut[8194] | xn[16][516] | S[16][516]   (pitch 516 -> conflict-free)
// ---------------------------------------------------------------------------
#define LNP 516
__global__ __launch_bounds__(512) void ln_s_kernel(const float* __restrict__ x,
                                                   const float* __restrict__ lw,
                                                   const float* __restrict__ lb) {
    extern __shared__ float sm[];
    float* lut_s = sm;                 // 8194
    float* xn_s  = sm + 8200;          // 16*516
    float* s_s   = xn_s + 16 * LNP;    // 16*516

    const int tid  = threadIdx.x;
    const int warp = tid >> 5;
    const int lane = tid & 31;
    const int rb   = blockIdx.x;           // 16-row block
    const int row  = rb * 16 + warp;
    const float* xr = x + (size_t)row * IN_DIM;

    for (int j = tid; j <= LUT_N; j += 512) lut_s[j] = g_lut[j];

    // stats
    float s = 0.f, ss = 0.f;
    for (int j = lane; j < IN_DIM; j += 32) {
        float v = xr[j];
        s += v;
        ss = fmaf(v, v, ss);
    }
#pragma unroll
    for (int o = 16; o > 0; o >>= 1) {
        s  += __shfl_xor_sync(0xFFFFFFFFu, s, o);
        ss += __shfl_xor_sync(0xFFFFFFFFu, ss, o);
    }
    const float mean = s * (1.f / (float)IN_DIM);
    const float var  = ss * (1.f / (float)IN_DIM) - mean * mean;
    const float rstd = rsqrtf(var + 1e-5f);
    __syncthreads();   // lut ready

    for (int p = 0; p < 4; p++) {
        const int c0 = p * 512;
        // compute panel
        for (int j = lane; j < 512; j += 32) {
            int c = c0 + j;
            float xn = fmaf((xr[c] - mean) * rstd, lw[c], lb[c]);
            xn_s[warp * LNP + j] = rtf32(xn);
            float t = (xn - LUT_LO) * LUT_INV;
            t = fminf(fmaxf(t, 0.f), (float)LUT_N - 0.001f);
            int i0 = (int)t;
            float fr = t - (float)i0;
            float v0 = lut_s[i0];
            s_s[warp * LNP + j] = rtf32(fmaf(fr, lut_s[i0 + 1] - v0, v0));
        }
        __syncthreads();
        // permuted coalesced writes: 64 kb x 32 lanes per panel, 4 slots/thread
#pragma unroll
        for (int i = 0; i < 4; i++) {
            int slot = tid + i * 512;          // < 2048
            int kb = slot >> 5, l = slot & 31;
            int r0 = l >> 2, cc = kb * 8 + (l & 3);
            float4 q;
            // xn half: kb_global = p*64 + kb
            q.x = xn_s[r0 * LNP + cc];
            q.y = xn_s[(r0 + 8) * LNP + cc];
            q.z = xn_s[r0 * LNP + cc + 4];
            q.w = xn_s[(r0 + 8) * LNP + cc + 4];
            *(float4*)(g_A + ((size_t)(rb * (size_t)NKB + p * 64 + kb) * 32 + l) * 4) = q;
            // S half: kb_global = 256 + p*64 + kb
            q.x = s_s[r0 * LNP + cc];
            q.y = s_s[(r0 + 8) * LNP + cc];
            q.z = s_s[r0 * LNP + cc + 4];
            q.w = s_s[(r0 + 8) * LNP + cc + 4];
            *(float4*)(g_A + ((size_t)(rb * (size_t)NKB + 256 + p * 64 + kb) * 32 + l) * 4) = q;
        }
        __syncthreads();
    }
}

// ---------------------------------------------------------------------------
// Kernel 3: B = [scale_base | Wd] -> g_B fragment-major, tf32-rounded.
// Block = 256 threads = 8 warps = 8 out-rows (one cb). 4 panels of 512.
// ---------------------------------------------------------------------------
__global__ __launch_bounds__(256) void build_b_kernel(const float* __restrict__ sw,
                                                      const float* __restrict__ sb) {
    __shared__ float w_s[8 * LNP];
    __shared__ float b_s[8 * LNP];
    const int tid  = threadIdx.x;
    const int warp = tid >> 5;
    const int lane = tid & 31;
    const int cb   = blockIdx.x;
    const int orow = cb * 8 + warp;

    for (int p = 0; p < 4; p++) {
        const int c0 = p * 512;
        for (int j = lane; j < 512; j += 32) {
            size_t idx = (size_t)orow * IN_DIM + c0 + j;
            const float4* q = (const float4*)(sw + idx * GRID_SZ);
            float4 w0 = q[0], w1 = q[1];
            float wd = ((w0.x + w0.y) + (w0.z + w0.w)) + ((w1.x + w1.y) + (w1.z + w1.w));
            w_s[warp * LNP + j] = rtf32(wd);
            b_s[warp * LNP + j] = rtf32(sb[idx]);
        }
        __syncthreads();
#pragma unroll
        for (int i = 0; i < 8; i++) {
            int slot = tid + i * 256;          // < 2048
            int kb = slot >> 5, l = slot & 31;
            int r0 = l >> 2, cc = kb * 8 + (l & 3);
            float2 pr;
            pr.x = b_s[r0 * LNP + cc];
            pr.y = b_s[r0 * LNP + cc + 4];
            *(float2*)(g_B + ((size_t)(cb * (size_t)NKB + p * 64 + kb) * 32 + l) * 2) = pr;
            pr.x = w_s[r0 * LNP + cc];
            pr.y = w_s[r0 * LNP + cc + 4];
            *(float2*)(g_B + ((size_t)(cb * (size_t)NKB + 256 + p * 64 + kb) * 32 + l) * 2) = pr;
        }
        __syncthreads();
    }
}

// ---------------------------------------------------------------------------
// Kernel 4: tf32 GEMM, fragment-major smem, BK=32, 3-stage cp.async
// ---------------------------------------------------------------------------
__device__ __forceinline__ void issue_slab(uint32_t sbase, int kt, int M0, int N0, int tid) {
    const int kb0 = kt * 4;
    // A: 8 rb x 4 kb x 32 l, float4 -> 1024 x 16B, 4 per thread
#pragma unroll
    for (int i = 0; i < 4; i++) {
        int slot = tid + i * 256;
        int rb = slot >> 7, kb = (slot >> 5) & 3, l = slot & 31;
        const float* g = g_A + ((size_t)((M0 / 16 + rb) * (size_t)NKB + kb0 + kb) * 32 + l) * 4;
        cp16(sbase + ((rb * 4 + kb) * 32 + l) * 16, g);
    }
    // B: 16 cb x 4 kb x 16 lane-pairs, float4 (covers 2 lanes) -> 1024 x 16B
#pragma unroll
    for (int i = 0; i < 4; i++) {
        int slot = tid + i * 256;
        int cb = slot >> 6, kb = (slot >> 4) & 3, lp = slot & 15;
        const float* g = g_B + ((size_t)((N0 / 8 + cb) * (size_t)NKB + kb0 + kb) * 32 + lp * 2) * 2;
        cp16(sbase + SB_OFF + ((cb * 4 + kb) * 32 + lp * 2) * 8, g);
    }
    asm volatile("cp.async.commit_group;" ::: "memory");
}

__global__ __launch_bounds__(256, 2) void gemm_kernel(const float* __restrict__ bias,
                                                      float* __restrict__ C) {
    extern __shared__ char smem[];
    const uint32_t sbase = smem_u32(smem);
    const int tid  = threadIdx.x;
    const int warp = tid >> 5;
    const int lane = tid & 31;
    const int wm = warp >> 1;        // 0..3
    const int wn = warp & 1;         // 0..1
    const int M0 = blockIdx.y * BM;
    const int N0 = blockIdx.x * BN;

    float c[2][8][4];
#pragma unroll
    for (int mi = 0; mi < 2; mi++)
#pragma unroll
        for (int ni = 0; ni < 8; ni++)
#pragma unroll
            for (int q = 0; q < 4; q++) c[mi][ni][q] = 0.f;

    issue_slab(sbase, 0, M0, N0, tid);
    issue_slab(sbase + STG_BYTES, 1, M0, N0, tid);

    const float* As = (const float*)smem;
    for (int kt = 0; kt < NT; kt++) {
        const int s = kt % NSTAGE;
        if (kt + 1 < NT)
            asm volatile("cp.async.wait_group 1;" ::: "memory");
        else
            asm volatile("cp.async.wait_group 0;" ::: "memory");
        __syncthreads();
        if (kt + 2 < NT)
            issue_slab(sbase + ((kt + 2) % NSTAGE) * STG_BYTES, kt + 2, M0, N0, tid);

        const float* Ast = As + (s * STG_BYTES) / 4;
        const float* Bst = Ast + SB_OFF / 4;
#pragma unroll
        for (int ks = 0; ks < 4; ks++) {
            float4 a0 = *(const float4*)(Ast + (((wm * 2 + 0) * 4 + ks) * 32 + lane) * 4);
            float4 a1 = *(const float4*)(Ast + (((wm * 2 + 1) * 4 + ks) * 32 + lane) * 4);
            float2 b[8];
#pragma unroll
            for (int ni = 0; ni < 8; ni++)
                b[ni] = *(const float2*)(Bst + (((wn * 8 + ni) * 4 + ks) * 32 + lane) * 2);
#pragma unroll
            for (int ni = 0; ni < 8; ni++) {
                mma_tf32(c[0][ni], a0, b[ni]);
                mma_tf32(c[1][ni], a1, b[ni]);
            }
        }
    }

    // epilogue
#pragma unroll
    for (int mi = 0; mi < 2; mi++) {
        const int r = M0 + wm * 32 + mi * 16 + (lane >> 2);
#pragma unroll
        for (int ni = 0; ni < 8; ni++) {
            const int cc = N0 + wn * 64 + ni * 8 + (lane & 3) * 2;
            float b0 = bias[cc], b1 = bias[cc + 1];
            float2 v0 = {c[mi][ni][0] + b0, c[mi][ni][1] + b1};
            float2 v1 = {c[mi][ni][2] + b0, c[mi][ni][3] + b1};
            *(float2*)(C + (size_t)r * OUT_DIM + cc)       = v0;
            *(float2*)(C + (size_t)(r + 8) * OUT_DIM + cc) = v1;
        }
    }
}

// ---------------------------------------------------------------------------
extern "C" void kernel_launch(void* const* d_in, const int* in_sizes, int n_in,
                              void* d_out, int out_size) {
    const float* x    = (const float*)d_in[0];
    const float* lw   = (const float*)d_in[1];
    const float* lb   = (const float*)d_in[2];
    const float* sw   = (const float*)d_in[3];
    const float* sb   = (const float*)d_in[4];
    const float* bias = (const float*)d_in[5];
    const float* beta = (const float*)d_in[6];
    const float* grid = (const float*)d_in[7];
    float* out = (float*)d_out;

    const int ln_smem = (8200 + 2 * 16 * LNP) * 4;
    cudaFuncSetAttribute(ln_s_kernel, cudaFuncAttributeMaxDynamicSharedMemorySize, ln_smem);
    cudaFuncSetAttribute(gemm_kernel, cudaFuncAttributeMaxDynamicSharedMemorySize,
                         NSTAGE * STG_BYTES);

    lut_build_kernel<<<(LUT_N + 256) / 256, 256>>>(grid, beta);
    ln_s_kernel<<<B_DIM / 16, 512, ln_smem>>>(x, lw, lb);
    build_b_kernel<<<OUT_DIM / 8, 256>>>(sw, sb);
    gemm_kernel<<<dim3(OUT_DIM / BN, B_DIM / BM), 256, NSTAGE * STG_BYTES>>>(bias, out);
}

// round 5
// speedup vs baseline: 2.4627x; 1.6698x over previous
#include <cuda_runtime.h>
#include <cuda_fp16.h>
#include <cstdint>
#include <cstring>

// Problem constants
#define B_DIM   4096
#define IN_DIM  2048
#define OUT_DIM 2048
#define K_DIM   4096           // concat: [xn | S]
#define GRID_SZ 8
#define NKB     (K_DIM / 16)   // 256 k-blocks of 16 (m16n8k16)

// LUT for S(xn) = sum_g exp(-beta*(xn-g)^2)
#define LUT_N    8192
#define LUT_LO   (-8.0f)
#define LUT_HI   (8.0f)
#define LUT_STEP ((LUT_HI - LUT_LO) / (float)LUT_N)
#define LUT_INV  ((float)LUT_N / (LUT_HI - LUT_LO))

// GEMM tiling
#define BM 128
#define BN 128
#define BK 64                  // 4 k16-blocks per slab
#define NT (K_DIM / BK)        // 64 k-slabs
#define NSTAGE 3
#define STG_BYTES 32768        // A 16K + B 16K
#define SB_OFF 16384

// ---------------------------------------------------------------------------
// Scratch: fragment-major fp16 operands (m16n8k16 register order)
//   A: [rb(256)][kb(256)][lane(32)][8 halves]  a0|a1|a2|a3
//   B: [cb(256)][kb(256)][lane(32)][4 halves]  b0|b1
// ---------------------------------------------------------------------------
__device__ __half g_A[(size_t)B_DIM * K_DIM];     // 32 MB
__device__ __half g_B[(size_t)OUT_DIM * K_DIM];   // 16 MB
__device__ float g_lut[LUT_N + 2];

__device__ __forceinline__ void cp16(uint32_t saddr, const void* g) {
    asm volatile("cp.async.cg.shared.global [%0], [%1], 16;" :: "r"(saddr), "l"(g));
}

__device__ __forceinline__ uint32_t smem_u32(const void* p) {
    uint32_t a;
    asm("{ .reg .u64 t; cvta.to.shared.u64 t, %1; cvt.u32.u64 %0, t; }" : "=r"(a) : "l"(p));
    return a;
}

__device__ __forceinline__ void mma_fp16(float* c, const uint4 a, const uint2 b) {
    asm volatile(
        "mma.sync.aligned.m16n8k16.row.col.f32.f16.f16.f32 "
        "{%0,%1,%2,%3}, {%4,%5,%6,%7}, {%8,%9}, {%0,%1,%2,%3};\n"
        : "+f"(c[0]), "+f"(c[1]), "+f"(c[2]), "+f"(c[3])
        : "r"(a.x), "r"(a.y), "r"(a.z), "r"(a.w), "r"(b.x), "r"(b.y));
}

__device__ __forceinline__ uint32_t h2u(float lo, float hi) {
    __half2 h = __floats2half2_rn(lo, hi);
    uint32_t u;
    memcpy(&u, &h, 4);
    return u;
}

// ---------------------------------------------------------------------------
// Kernel 1: build S lookup table
// ---------------------------------------------------------------------------
__global__ void lut_build_kernel(const float* __restrict__ grid,
                                 const float* __restrict__ rbf_beta) {
    int j = blockIdx.x * 256 + threadIdx.x;
    if (j > LUT_N) return;
    float beta = fminf(fmaxf(rbf_beta[0], 0.5f), 6.0f);
    float xx = LUT_LO + (float)j * LUT_STEP;
    float s = 0.f;
#pragma unroll
    for (int g = 0; g < GRID_SZ; g++) {
        float d = xx - grid[g];
        s += expf(-beta * d * d);
    }
    g_lut[j] = s;
}

// ---------------------------------------------------------------------------
// Kernel 2: LayerNorm + S -> g_A fragment-major fp16.
// Block = 512 threads = 16 warps = 16 rows (one rb). 4 column panels of 512.
// ---------------------------------------------------------------------------
#define LNP 516
__global__ __launch_bounds__(512) void ln_s_kernel(const float* __restrict__ x,
                                                   const float* __restrict__ lw,
                                                   const float* __restrict__ lb) {
    extern __shared__ float sm[];
    float* lut_s = sm;                 // 8194
    float* xn_s  = sm + 8200;          // 16*516
    float* s_s   = xn_s + 16 * LNP;    // 16*516

    const int tid  = threadIdx.x;
    const int warp = tid >> 5;
    const int lane = tid & 31;
    const int rb   = blockIdx.x;           // 16-row block
    const int row  = rb * 16 + warp;
    const float* xr = x + (size_t)row * IN_DIM;

    for (int j = tid; j <= LUT_N; j += 512) lut_s[j] = g_lut[j];

    float s = 0.f, ss = 0.f;
    for (int j = lane; j < IN_DIM; j += 32) {
        float v = xr[j];
        s += v;
        ss = fmaf(v, v, ss);
    }
#pragma unroll
    for (int o = 16; o > 0; o >>= 1) {
        s  += __shfl_xor_sync(0xFFFFFFFFu, s, o);
        ss += __shfl_xor_sync(0xFFFFFFFFu, ss, o);
    }
    const float mean = s * (1.f / (float)IN_DIM);
    const float var  = ss * (1.f / (float)IN_DIM) - mean * mean;
    const float rstd = rsqrtf(var + 1e-5f);
    __syncthreads();   // lut ready

    for (int p = 0; p < 4; p++) {
        const int c0 = p * 512;
        for (int j = lane; j < 512; j += 32) {
            int c = c0 + j;
            float xn = fmaf((xr[c] - mean) * rstd, lw[c], lb[c]);
            xn_s[warp * LNP + j] = xn;
            float t = (xn - LUT_LO) * LUT_INV;
            t = fminf(fmaxf(t, 0.f), (float)LUT_N - 0.001f);
            int i0 = (int)t;
            float fr = t - (float)i0;
            float v0 = lut_s[i0];
            s_s[warp * LNP + j] = fmaf(fr, lut_s[i0 + 1] - v0, v0);
        }
        __syncthreads();
        // permute: panel has 32 k16-blocks x 32 lanes; 8 halves (16B) per slot
#pragma unroll
        for (int i = 0; i < 2; i++) {
            int slot = tid + i * 512;          // < 1024
            int kb = slot >> 5, l = slot & 31;
            int r0 = l >> 2;
            int cc = kb * 16 + (l & 3) * 2;    // within panel
            uint4 u;
            const float* xs = xn_s;
            u.x = h2u(xs[r0 * LNP + cc],           xs[r0 * LNP + cc + 1]);
            u.y = h2u(xs[(r0 + 8) * LNP + cc],     xs[(r0 + 8) * LNP + cc + 1]);
            u.z = h2u(xs[r0 * LNP + cc + 8],       xs[r0 * LNP + cc + 9]);
            u.w = h2u(xs[(r0 + 8) * LNP + cc + 8], xs[(r0 + 8) * LNP + cc + 9]);
            *(uint4*)(g_A + ((size_t)(rb * (size_t)NKB + p * 32 + kb) * 32 + l) * 8) = u;
            const float* qs = s_s;
            u.x = h2u(qs[r0 * LNP + cc],           qs[r0 * LNP + cc + 1]);
            u.y = h2u(qs[(r0 + 8) * LNP + cc],     qs[(r0 + 8) * LNP + cc + 1]);
            u.z = h2u(qs[r0 * LNP + cc + 8],       qs[r0 * LNP + cc + 9]);
            u.w = h2u(qs[(r0 + 8) * LNP + cc + 8], qs[(r0 + 8) * LNP + cc + 9]);
            *(uint4*)(g_A + ((size_t)(rb * (size_t)NKB + 128 + p * 32 + kb) * 32 + l) * 8) = u;
        }
        __syncthreads();
    }
}

// ---------------------------------------------------------------------------
// Kernel 3: B = [scale_base | Wd] -> g_B fragment-major fp16.
// Block = 256 threads = 8 warps = 8 out-rows (one cb). 4 panels of 512.
// ---------------------------------------------------------------------------
__global__ __launch_bounds__(256) void build_b_kernel(const float* __restrict__ sw,
                                                      const float* __restrict__ sb) {
    __shared__ float w_s[8 * LNP];
    __shared__ float b_s[8 * LNP];
    const int tid  = threadIdx.x;
    const int warp = tid >> 5;
    const int lane = tid & 31;
    const int cb   = blockIdx.x;
    const int orow = cb * 8 + warp;

    for (int p = 0; p < 4; p++) {
        const int c0 = p * 512;
        for (int j = lane; j < 512; j += 32) {
            size_t idx = (size_t)orow * IN_DIM + c0 + j;
            const float4* q = (const float4*)(sw + idx * GRID_SZ);
            float4 w0 = q[0], w1 = q[1];
            w_s[warp * LNP + j] =
                ((w0.x + w0.y) + (w0.z + w0.w)) + ((w1.x + w1.y) + (w1.z + w1.w));
            b_s[warp * LNP + j] = sb[idx];
        }
        __syncthreads();
        // permute: 32 k16-blocks x 32 lanes; 4 halves (8B) per slot
#pragma unroll
        for (int i = 0; i < 4; i++) {
            int slot = tid + i * 256;          // < 1024
            int kb = slot >> 5, l = slot & 31;
            int col = l >> 2;                  // out-row within cb
            int kk = kb * 16 + (l & 3) * 2;    // k within panel
            uint2 v;
            v.x = h2u(b_s[col * LNP + kk],     b_s[col * LNP + kk + 1]);
            v.y = h2u(b_s[col * LNP + kk + 8], b_s[col * LNP + kk + 9]);
            *(uint2*)(g_B + ((size_t)(cb * (size_t)NKB + p * 32 + kb) * 32 + l) * 4) = v;
            v.x = h2u(w_s[col * LNP + kk],     w_s[col * LNP + kk + 1]);
            v.y = h2u(w_s[col * LNP + kk + 8], w_s[col * LNP + kk + 9]);
            *(uint2*)(g_B + ((size_t)(cb * (size_t)NKB + 128 + p * 32 + kb) * 32 + l) * 4) = v;
        }
        __syncthreads();
    }
}

// ---------------------------------------------------------------------------
// Kernel 4: fp16 GEMM, fragment-major smem, BK=64, 3-stage cp.async
// ---------------------------------------------------------------------------
__device__ __forceinline__ void issue_slab(uint32_t sbase, int kt, int M0, int N0, int tid) {
    const int kb0 = kt * 4;
    // A: 8 rb x 4 kb x 32 lanes, 16B each -> 1024 slots, 4/thread
#pragma unroll
    for (int i = 0; i < 4; i++) {
        int slot = tid + i * 256;
        int rb = slot >> 7, kb = (slot >> 5) & 3, l = slot & 31;
        const __half* g = g_A + ((size_t)((M0 / 16 + rb) * (size_t)NKB + kb0 + kb) * 32 + l) * 8;
        cp16(sbase + ((rb * 4 + kb) * 32 + l) * 16, g);
    }
    // B: 16 cb x 4 kb x 16 lane-pairs, 16B each -> 1024 slots, 4/thread
#pragma unroll
    for (int i = 0; i < 4; i++) {
        int slot = tid + i * 256;
        int cb = slot >> 6, kb = (slot >> 4) & 3, lp = slot & 15;
        const __half* g = g_B + ((size_t)((N0 / 8 + cb) * (size_t)NKB + kb0 + kb) * 32 + lp * 2) * 4;
        cp16(sbase + SB_OFF + ((cb * 4 + kb) * 32 + lp * 2) * 8, g);
    }
    asm volatile("cp.async.commit_group;" ::: "memory");
}

__global__ __launch_bounds__(256, 2) void gemm_kernel(const float* __restrict__ bias,
                                                      float* __restrict__ C) {
    extern __shared__ char smem[];
    const uint32_t sbase = smem_u32(smem);
    const int tid  = threadIdx.x;
    const int warp = tid >> 5;
    const int lane = tid & 31;
    const int wm = warp >> 1;        // 0..3
    const int wn = warp & 1;         // 0..1
    const int M0 = blockIdx.y * BM;
    const int N0 = blockIdx.x * BN;

    float c[2][8][4];
#pragma unroll
    for (int mi = 0; mi < 2; mi++)
#pragma unroll
        for (int ni = 0; ni < 8; ni++)
#pragma unroll
            for (int q = 0; q < 4; q++) c[mi][ni][q] = 0.f;

    issue_slab(sbase, 0, M0, N0, tid);
    issue_slab(sbase + STG_BYTES, 1, M0, N0, tid);

    for (int kt = 0; kt < NT; kt++) {
        const int s = kt % NSTAGE;
        if (kt + 1 < NT)
            asm volatile("cp.async.wait_group 1;" ::: "memory");
        else
            asm volatile("cp.async.wait_group 0;" ::: "memory");
        __syncthreads();
        if (kt + 2 < NT)
            issue_slab(sbase + ((kt + 2) % NSTAGE) * STG_BYTES, kt + 2, M0, N0, tid);

        const char* Ast = smem + s * STG_BYTES;
        const char* Bst = Ast + SB_OFF;
#pragma unroll
        for (int ks = 0; ks < 4; ks++) {
            uint4 a0 = *(const uint4*)(Ast + ((wm * 2 + 0) * 4 + ks) * 512 + lane * 16);
            uint4 a1 = *(const uint4*)(Ast + ((wm * 2 + 1) * 4 + ks) * 512 + lane * 16);
            uint2 b[8];
#pragma unroll
            for (int ni = 0; ni < 8; ni++)
                b[ni] = *(const uint2*)(Bst + ((wn * 8 + ni) * 4 + ks) * 256 + lane * 8);
#pragma unroll
            for (int ni = 0; ni < 8; ni++) {
                mma_fp16(c[0][ni], a0, b[ni]);
                mma_fp16(c[1][ni], a1, b[ni]);
            }
        }
    }

    // epilogue
#pragma unroll
    for (int mi = 0; mi < 2; mi++) {
        const int r = M0 + wm * 32 + mi * 16 + (lane >> 2);
#pragma unroll
        for (int ni = 0; ni < 8; ni++) {
            const int cc = N0 + wn * 64 + ni * 8 + (lane & 3) * 2;
            float b0 = bias[cc], b1 = bias[cc + 1];
            float2 v0 = {c[mi][ni][0] + b0, c[mi][ni][1] + b1};
            float2 v1 = {c[mi][ni][2] + b0, c[mi][ni][3] + b1};
            *(float2*)(C + (size_t)r * OUT_DIM + cc)       = v0;
            *(float2*)(C + (size_t)(r + 8) * OUT_DIM + cc) = v1;
        }
    }
}

// ---------------------------------------------------------------------------
extern "C" void kernel_launch(void* const* d_in, const int* in_sizes, int n_in,
                              void* d_out, int out_size) {
    const float* x    = (const float*)d_in[0];
    const float* lw   = (const float*)d_in[1];
    const float* lb   = (const float*)d_in[2];
    const float* sw   = (const float*)d_in[3];
    const float* sb   = (const float*)d_in[4];
    const float* bias = (const float*)d_in[5];
    const float* beta = (const float*)d_in[6];
    const float* grid = (const float*)d_in[7];
    float* out = (float*)d_out;

    const int ln_smem = (8200 + 2 * 16 * LNP) * 4;
    cudaFuncSetAttribute(ln_s_kernel, cudaFuncAttributeMaxDynamicSharedMemorySize, ln_smem);
    cudaFuncSetAttribute(gemm_kernel, cudaFuncAttributeMaxDynamicSharedMemorySize,
                         NSTAGE * STG_BYTES);

    lut_build_kernel<<<(LUT_N + 256) / 256, 256>>>(grid, beta);
    ln_s_kernel<<<B_DIM / 16, 512, ln_smem>>>(x, lw, lb);
    build_b_kernel<<<OUT_DIM / 8, 256>>>(sw, sb);
    gemm_kernel<<<dim3(OUT_DIM / BN, B_DIM / BM), 256, NSTAGE * STG_BYTES>>>(bias, out);
}

// round 6
// speedup vs baseline: 2.5250x; 1.0253x over previous
#include <cuda_runtime.h>
#include <cuda_fp16.h>
#include <cstdint>
#include <cstring>

// Problem constants
#define B_DIM   4096
#define IN_DIM  2048
#define OUT_DIM 2048
#define K_DIM   4096           // concat: [xn | S]
#define GRID_SZ 8
#define NKB     (K_DIM / 16)   // 256 k-blocks of 16 (m16n8k16)

// LUT for S(xn) = sum_g exp(-beta*(xn-g)^2)
#define LUT_N    8192
#define LUT_LO   (-8.0f)
#define LUT_HI   (8.0f)
#define LUT_STEP ((LUT_HI - LUT_LO) / (float)LUT_N)
#define LUT_INV  ((float)LUT_N / (LUT_HI - LUT_LO))

// GEMM tiling: CTA 256x128, warp 64x64, 8 warps, BK=64, 4 stages
#define BM 256
#define BN 128
#define BK 64
#define NT (K_DIM / BK)        // 64 k-slabs
#define NSTAGE 4
#define STG_BYTES 49152        // A 32K + B 16K
#define SB_OFF 32768
#define GEMM_SMEM (NSTAGE * STG_BYTES)   // 196608

// ---------------------------------------------------------------------------
// Scratch: fragment-major fp16 operands (m16n8k16 register order)
//   A: [rb(256)][kb(256)][lane(32)][8 halves]  a0|a1|a2|a3
//   B: [cb(256)][kb(256)][lane(32)][4 halves]  b0|b1
// ---------------------------------------------------------------------------
__device__ __half g_A[(size_t)B_DIM * K_DIM];     // 32 MB
__device__ __half g_B[(size_t)OUT_DIM * K_DIM];   // 16 MB
__device__ float g_lut[LUT_N + 2];

__device__ __forceinline__ void cp16(uint32_t saddr, const void* g) {
    asm volatile("cp.async.cg.shared.global [%0], [%1], 16;" :: "r"(saddr), "l"(g));
}

__device__ __forceinline__ uint32_t smem_u32(const void* p) {
    uint32_t a;
    asm("{ .reg .u64 t; cvta.to.shared.u64 t, %1; cvt.u32.u64 %0, t; }" : "=r"(a) : "l"(p));
    return a;
}

__device__ __forceinline__ void mma_fp16(float* c, const uint4 a, const uint2 b) {
    asm volatile(
        "mma.sync.aligned.m16n8k16.row.col.f32.f16.f16.f32 "
        "{%0,%1,%2,%3}, {%4,%5,%6,%7}, {%8,%9}, {%0,%1,%2,%3};\n"
        : "+f"(c[0]), "+f"(c[1]), "+f"(c[2]), "+f"(c[3])
        : "r"(a.x), "r"(a.y), "r"(a.z), "r"(a.w), "r"(b.x), "r"(b.y));
}

__device__ __forceinline__ uint32_t h2u(float lo, float hi) {
    __half2 h = __floats2half2_rn(lo, hi);
    uint32_t u;
    memcpy(&u, &h, 4);
    return u;
}

// ---------------------------------------------------------------------------
// Kernel 1: build S lookup table
// ---------------------------------------------------------------------------
__global__ void lut_build_kernel(const float* __restrict__ grid,
                                 const float* __restrict__ rbf_beta) {
    int j = blockIdx.x * 256 + threadIdx.x;
    if (j > LUT_N) return;
    float beta = fminf(fmaxf(rbf_beta[0], 0.5f), 6.0f);
    float xx = LUT_LO + (float)j * LUT_STEP;
    float s = 0.f;
#pragma unroll
    for (int g = 0; g < GRID_SZ; g++) {
        float d = xx - grid[g];
        s += expf(-beta * d * d);
    }
    g_lut[j] = s;
}

// ---------------------------------------------------------------------------
// Kernel 2 (merged prep): interleaved grid of 384 blocks, 512 threads.
//   blocks with bid%3 != 2  (256 of them): LayerNorm + S -> g_A
//   blocks with bid%3 == 2  (128 of them): spline reduce + scale_base -> g_B
// ---------------------------------------------------------------------------
#define LNP 516
#define PREP_SMEM ((8200 + 2 * 16 * LNP) * 4)

__global__ __launch_bounds__(512) void prep_kernel(const float* __restrict__ x,
                                                   const float* __restrict__ lw,
                                                   const float* __restrict__ lb,
                                                   const float* __restrict__ sw,
                                                   const float* __restrict__ sb) {
    extern __shared__ float sm[];
    const int bid  = blockIdx.x;
    const int tid  = threadIdx.x;
    const int warp = tid >> 5;
    const int lane = tid & 31;

    if (bid % 3 != 2) {
        // ---------------- LayerNorm + S role ----------------
        const int rb = (bid / 3) * 2 + (bid % 3);     // 0..255
        float* lut_s = sm;                 // 8194
        float* xn_s  = sm + 8200;          // 16*516
        float* s_s   = xn_s + 16 * LNP;    // 16*516

        const int row  = rb * 16 + warp;
        const float* xr = x + (size_t)row * IN_DIM;

        for (int j = tid; j <= LUT_N; j += 512) lut_s[j] = g_lut[j];

        float s = 0.f, ss = 0.f;
        for (int j = lane; j < IN_DIM; j += 32) {
            float v = xr[j];
            s += v;
            ss = fmaf(v, v, ss);
        }
#pragma unroll
        for (int o = 16; o > 0; o >>= 1) {
            s  += __shfl_xor_sync(0xFFFFFFFFu, s, o);
            ss += __shfl_xor_sync(0xFFFFFFFFu, ss, o);
        }
        const float mean = s * (1.f / (float)IN_DIM);
        const float var  = ss * (1.f / (float)IN_DIM) - mean * mean;
        const float rstd = rsqrtf(var + 1e-5f);
        __syncthreads();   // lut ready

        for (int p = 0; p < 4; p++) {
            const int c0 = p * 512;
            for (int j = lane; j < 512; j += 32) {
                int c = c0 + j;
                float xn = fmaf((xr[c] - mean) * rstd, lw[c], lb[c]);
                xn_s[warp * LNP + j] = xn;
                float t = (xn - LUT_LO) * LUT_INV;
                t = fminf(fmaxf(t, 0.f), (float)LUT_N - 0.001f);
                int i0 = (int)t;
                float fr = t - (float)i0;
                float v0 = lut_s[i0];
                s_s[warp * LNP + j] = fmaf(fr, lut_s[i0 + 1] - v0, v0);
            }
            __syncthreads();
#pragma unroll
            for (int i = 0; i < 2; i++) {
                int slot = tid + i * 512;          // < 1024
                int kb = slot >> 5, l = slot & 31;
                int r0 = l >> 2;
                int cc = kb * 16 + (l & 3) * 2;
                uint4 u;
                const float* xs = xn_s;
                u.x = h2u(xs[r0 * LNP + cc],           xs[r0 * LNP + cc + 1]);
                u.y = h2u(xs[(r0 + 8) * LNP + cc],     xs[(r0 + 8) * LNP + cc + 1]);
                u.z = h2u(xs[r0 * LNP + cc + 8],       xs[r0 * LNP + cc + 9]);
                u.w = h2u(xs[(r0 + 8) * LNP + cc + 8], xs[(r0 + 8) * LNP + cc + 9]);
                *(uint4*)(g_A + ((size_t)(rb * (size_t)NKB + p * 32 + kb) * 32 + l) * 8) = u;
                const float* qs = s_s;
                u.x = h2u(qs[r0 * LNP + cc],           qs[r0 * LNP + cc + 1]);
                u.y = h2u(qs[(r0 + 8) * LNP + cc],     qs[(r0 + 8) * LNP + cc + 1]);
                u.z = h2u(qs[r0 * LNP + cc + 8],       qs[r0 * LNP + cc + 9]);
                u.w = h2u(qs[(r0 + 8) * LNP + cc + 8], qs[(r0 + 8) * LNP + cc + 9]);
                *(uint4*)(g_A + ((size_t)(rb * (size_t)NKB + 128 + p * 32 + kb) * 32 + l) * 8) = u;
            }
            __syncthreads();
        }
    } else {
        // ---------------- B-build role ----------------
        const int build_id = bid / 3;                 // 0..127 (16 out-rows each)
        float* w_s = sm + 8200;            // 16*516
        float* b_s = w_s + 16 * LNP;       // 16*516
        const int orow = build_id * 16 + warp;

        for (int p = 0; p < 4; p++) {
            const int c0 = p * 512;
            for (int j = lane; j < 512; j += 32) {
                size_t idx = (size_t)orow * IN_DIM + c0 + j;
                const float4* q = (const float4*)(sw + idx * GRID_SZ);
                float4 w0 = q[0], w1 = q[1];
                w_s[warp * LNP + j] =
                    ((w0.x + w0.y) + (w0.z + w0.w)) + ((w1.x + w1.y) + (w1.z + w1.w));
                b_s[warp * LNP + j] = sb[idx];
            }
            __syncthreads();
            // permute: 2 half-blocks x 32 kb x 32 lanes = 2048 slots
#pragma unroll
            for (int i = 0; i < 4; i++) {
                int slot = tid + i * 512;
                int half = slot >> 10;
                int rem  = slot & 1023;
                int kb = rem >> 5, l = rem & 31;
                int colr = half * 8 + (l >> 2);        // smem row
                int kk = kb * 16 + (l & 3) * 2;
                size_t cb = (size_t)build_id * 2 + half;
                uint2 v;
                v.x = h2u(b_s[colr * LNP + kk],     b_s[colr * LNP + kk + 1]);
                v.y = h2u(b_s[colr * LNP + kk + 8], b_s[colr * LNP + kk + 9]);
                *(uint2*)(g_B + ((cb * NKB + p * 32 + kb) * 32 + l) * 4) = v;
                v.x = h2u(w_s[colr * LNP + kk],     w_s[colr * LNP + kk + 1]);
                v.y = h2u(w_s[colr * LNP + kk + 8], w_s[colr * LNP + kk + 9]);
                *(uint2*)(g_B + ((cb * NKB + 128 + p * 32 + kb) * 32 + l) * 4) = v;
            }
            __syncthreads();
        }
    }
}

// ---------------------------------------------------------------------------
// Kernel 3: fp16 GEMM, CTA 256x128, warp 64x64, 4-stage cp.async
// ---------------------------------------------------------------------------
__device__ __forceinline__ void issue_slab(uint32_t sbase, int kt, int M0, int N0, int tid) {
    const int kb0 = kt * 4;
    // A: 16 rb x 4 kb x 32 lanes, 16B each -> 2048 slots, 8/thread
#pragma unroll
    for (int i = 0; i < 8; i++) {
        int slot = tid + i * 256;
        int rb = slot >> 7, kb = (slot >> 5) & 3, l = slot & 31;
        const __half* g = g_A + ((size_t)((M0 / 16 + rb) * (size_t)NKB + kb0 + kb) * 32 + l) * 8;
        cp16(sbase + ((rb * 4 + kb) * 32 + l) * 16, g);
    }
    // B: 16 cb x 4 kb x 16 lane-pairs, 16B each -> 1024 slots, 4/thread
#pragma unroll
    for (int i = 0; i < 4; i++) {
        int slot = tid + i * 256;
        int cb = slot >> 6, kb = (slot >> 4) & 3, lp = slot & 15;
        const __half* g = g_B + ((size_t)((N0 / 8 + cb) * (size_t)NKB + kb0 + kb) * 32 + lp * 2) * 4;
        cp16(sbase + SB_OFF + ((cb * 4 + kb) * 32 + lp * 2) * 8, g);
    }
    asm volatile("cp.async.commit_group;" ::: "memory");
}

__global__ __launch_bounds__(256) void gemm_kernel(const float* __restrict__ bias,
                                                   float* __restrict__ C) {
    extern __shared__ char smem[];
    const uint32_t sbase = smem_u32(smem);
    const int tid  = threadIdx.x;
    const int warp = tid >> 5;
    const int lane = tid & 31;
    const int wm = warp >> 1;        // 0..3  (64-row block)
    const int wn = warp & 1;         // 0..1  (64-col block)
    const int M0 = blockIdx.y * BM;
    const int N0 = blockIdx.x * BN;

    float c[4][8][4];
#pragma unroll
    for (int mi = 0; mi < 4; mi++)
#pragma unroll
        for (int ni = 0; ni < 8; ni++)
#pragma unroll
            for (int q = 0; q < 4; q++) c[mi][ni][q] = 0.f;

    issue_slab(sbase, 0, M0, N0, tid);
    issue_slab(sbase + STG_BYTES, 1, M0, N0, tid);
    issue_slab(sbase + 2 * STG_BYTES, 2, M0, N0, tid);

    for (int kt = 0; kt < NT; kt++) {
        const int s = kt & 3;
        if (kt < NT - 2)
            asm volatile("cp.async.wait_group 2;" ::: "memory");
        else if (kt == NT - 2)
            asm volatile("cp.async.wait_group 1;" ::: "memory");
        else
            asm volatile("cp.async.wait_group 0;" ::: "memory");
        __syncthreads();
        if (kt + 3 < NT)
            issue_slab(sbase + ((kt + 3) & 3) * STG_BYTES, kt + 3, M0, N0, tid);

        const char* Ast = smem + s * STG_BYTES;
        const char* Bst = Ast + SB_OFF;
#pragma unroll
        for (int ks = 0; ks < 4; ks++) {
            uint4 a[4];
#pragma unroll
            for (int mi = 0; mi < 4; mi++)
                a[mi] = *(const uint4*)(Ast + ((wm * 4 + mi) * 4 + ks) * 512 + lane * 16);
            uint2 b[8];
#pragma unroll
            for (int ni = 0; ni < 8; ni++)
                b[ni] = *(const uint2*)(Bst + ((wn * 8 + ni) * 4 + ks) * 256 + lane * 8);
#pragma unroll
            for (int mi = 0; mi < 4; mi++)
#pragma unroll
                for (int ni = 0; ni < 8; ni++)
                    mma_fp16(c[mi][ni], a[mi], b[ni]);
        }
    }

    // epilogue
#pragma unroll
    for (int mi = 0; mi < 4; mi++) {
        const int r = M0 + wm * 64 + mi * 16 + (lane >> 2);
#pragma unroll
        for (int ni = 0; ni < 8; ni++) {
            const int cc = N0 + wn * 64 + ni * 8 + (lane & 3) * 2;
            float b0 = bias[cc], b1 = bias[cc + 1];
            float2 v0 = {c[mi][ni][0] + b0, c[mi][ni][1] + b1};
            float2 v1 = {c[mi][ni][2] + b0, c[mi][ni][3] + b1};
            *(float2*)(C + (size_t)r * OUT_DIM + cc)       = v0;
            *(float2*)(C + (size_t)(r + 8) * OUT_DIM + cc) = v1;
        }
    }
}

// ---------------------------------------------------------------------------
extern "C" void kernel_launch(void* const* d_in, const int* in_sizes, int n_in,
                              void* d_out, int out_size) {
    const float* x    = (const float*)d_in[0];
    const float* lw   = (const float*)d_in[1];
    const float* lb   = (const float*)d_in[2];
    const float* sw   = (const float*)d_in[3];
    const float* sb   = (const float*)d_in[4];
    const float* bias = (const float*)d_in[5];
    const float* beta = (const float*)d_in[6];
    const float* grid = (const float*)d_in[7];
    float* out = (float*)d_out;

    cudaFuncSetAttribute(prep_kernel, cudaFuncAttributeMaxDynamicSharedMemorySize, PREP_SMEM);
    cudaFuncSetAttribute(gemm_kernel, cudaFuncAttributeMaxDynamicSharedMemorySize, GEMM_SMEM);

    lut_build_kernel<<<(LUT_N + 256) / 256, 256>>>(grid, beta);
    prep_kernel<<<384, 512, PREP_SMEM>>>(x, lw, lb, sw, sb);
    gemm_kernel<<<dim3(OUT_DIM / BN, B_DIM / BM), 256, GEMM_SMEM>>>(bias, out);
}